// round 10
// baseline (speedup 1.0000x reference)
#include <cuda_runtime.h>
#include <cuda_bf16.h>
#include <math.h>
#include <stdint.h>

// Problem constants
#define BB 32
#define TT 577
#define EE 1024
#define HH 16
#define DD 64
#define MM (BB * TT)   // 18464 rows

// Scratch (alloc-free rule: __device__ globals)
__device__ float g_q[(size_t)MM * EE];
__device__ float g_k[(size_t)MM * EE];
__device__ float g_v[(size_t)MM * EE];
__device__ float g_att[(size_t)MM * EE];

// ---------------------------------------------------------------------------
// helpers
// ---------------------------------------------------------------------------
// 2-op split: hi = tf32_rna(x); lo = x - hi as raw fp32 bits (lo rides RZ).
__device__ __forceinline__ void split_u(float x, uint32_t& hi, uint32_t& lo) {
    uint32_t uh;
    asm("cvt.rna.tf32.f32 %0, %1;" : "=r"(uh) : "f"(x));
    hi = uh;
    lo = __float_as_uint(x - __uint_as_float(uh));
}

// hi-only convert for B operands (2xTF32: a*b ~= aH*bH + aL*bH)
__device__ __forceinline__ uint32_t cvt_hi(float x) {
    uint32_t uh;
    asm("cvt.rna.tf32.f32 %0, %1;" : "=r"(uh) : "f"(x));
    return uh;
}
__device__ __forceinline__ float tf32f(float x) {
    uint32_t u;
    asm("cvt.rna.tf32.f32 %0, %1;" : "=r"(u) : "f"(x));
    return __uint_as_float(u);
}

__device__ __forceinline__ void mma_tf32(float* acc,
                                         uint32_t a0, uint32_t a1, uint32_t a2, uint32_t a3,
                                         uint32_t b0, uint32_t b1) {
    asm volatile(
        "mma.sync.aligned.m16n8k8.row.col.f32.tf32.tf32.f32 "
        "{%0,%1,%2,%3}, {%4,%5,%6,%7}, {%8,%9}, {%0,%1,%2,%3};\n"
        : "+f"(acc[0]), "+f"(acc[1]), "+f"(acc[2]), "+f"(acc[3])
        : "r"(a0), "r"(a1), "r"(a2), "r"(a3), "r"(b0), "r"(b1));
}

__device__ __forceinline__ uint32_t smem_u32(const void* p) {
    return (uint32_t)__cvta_generic_to_shared(p);
}

// cp.async 16B with zero-fill when pred is false (src not accessed)
__device__ __forceinline__ void cp16(uint32_t dst, const void* src, bool pred) {
    asm volatile("cp.async.cg.shared.global [%0], [%1], 16, %2;\n"
                 :: "r"(dst), "l"(src), "r"(pred ? 16 : 0));
}
#define CP_COMMIT() asm volatile("cp.async.commit_group;\n" ::: "memory")
#define CP_WAIT0()  asm volatile("cp.async.wait_group 0;\n" ::: "memory")

// ---------------------------------------------------------------------------
// GEMM (2xTF32): C[M,1024] = A[M,1024] @ B[1024,1024] + bias
// Block tile 128x256, BK=32, 16 warps (2x8), warp tile 64x32.
// 512 threads -> 4 warps/SMSP to hide LDS/cvt->MMA latency.
// Dynamic smem: AS[2][128][36] + BS[2][32][264] = 104448 B. 1 CTA/SM.
// ---------------------------------------------------------------------------
#define GBN 256
#define GA_STRIDE 36
#define GB_STRIDE 264
#define GA_BUF (128 * GA_STRIDE)   // 4608 floats
#define GB_BUF (32 * GB_STRIDE)    // 8448 floats
#define GSMEM_FLOATS (2 * (GA_BUF + GB_BUF))   // 26112

__global__ __launch_bounds__(512, 1) void gemm_tf32x2(
    const float* __restrict__ A, const float* __restrict__ B,
    const float* __restrict__ bias, float* __restrict__ C, int M)
{
    extern __shared__ float sm[];
    float* AS = sm;                   // [2][128][36]
    float* BS = AS + 2 * GA_BUF;      // [2][32][264]
    const uint32_t sA = smem_u32(AS);
    const uint32_t sB = smem_u32(BS);

    const int tid  = threadIdx.x;
    const int lane = tid & 31;
    const int wid  = tid >> 5;        // 0..15
    const int g    = lane >> 2;       // 0..7
    const int tg   = lane & 3;        // 0..3
    const int wm   = (wid >> 3) * 64; // warp row offset (0/64)
    const int wn   = (wid & 7) * 32;  // warp col offset (0..224)
    const int rowBase = blockIdx.y * 128;
    const int colBase = blockIdx.x * GBN;

    float acc[4][4][4];
    #pragma unroll
    for (int mf = 0; mf < 4; mf++)
        #pragma unroll
        for (int nf = 0; nf < 4; nf++)
            #pragma unroll
            for (int c = 0; c < 4; c++) acc[mf][nf][c] = 0.f;

    auto issue = [&](int buf, int k0) {
        // A tile: 128 rows x 8 chunks = 1024
        #pragma unroll
        for (int i = 0; i < 2; i++) {
            const int idx = tid + i * 512;
            const int r = idx >> 3;
            const int c4 = (idx & 7) * 4;
            const int gr = rowBase + r;
            cp16(sA + (uint32_t)(buf * GA_BUF + r * GA_STRIDE + c4) * 4,
                 A + (size_t)gr * EE + k0 + c4, gr < M);
        }
        // B tile: 32 rows x 64 chunks = 2048
        #pragma unroll
        for (int i = 0; i < 4; i++) {
            const int idx = tid + i * 512;
            const int r = idx >> 6;
            const int c4 = (idx & 63) * 4;
            cp16(sB + (uint32_t)(buf * GB_BUF + r * GB_STRIDE + c4) * 4,
                 B + (size_t)(k0 + r) * EE + colBase + c4, true);
        }
        CP_COMMIT();
    };

    issue(0, 0);
    CP_WAIT0();
    __syncthreads();

    int buf = 0;
    for (int k0 = 0; k0 < EE; k0 += 32) {
        const bool more = (k0 + 32 < EE);
        if (more) issue(buf ^ 1, k0 + 32);   // DMA overlaps compute below

        const float* as = AS + buf * GA_BUF;
        const float* bs = BS + buf * GB_BUF;

        #pragma unroll
        for (int ks = 0; ks < 4; ks++) {
            uint32_t bHf[4][2];
            const int br0 = (ks * 8 + tg) * GB_STRIDE;
            const int br1 = br0 + 4 * GB_STRIDE;
            #pragma unroll
            for (int nf = 0; nf < 4; nf++) {
                const int col = wn + nf * 8 + g;
                bHf[nf][0] = cvt_hi(bs[br0 + col]);
                bHf[nf][1] = cvt_hi(bs[br1 + col]);
            }
            #pragma unroll
            for (int mf = 0; mf < 4; mf++) {
                const int r0 = (wm + mf * 16 + g) * GA_STRIDE + ks * 8 + tg;
                const int r1 = r0 + 8 * GA_STRIDE;
                uint32_t aH0, aH1, aH2, aH3, aL0, aL1, aL2, aL3;
                split_u(as[r0],     aH0, aL0);
                split_u(as[r1],     aH1, aL1);
                split_u(as[r0 + 4], aH2, aL2);
                split_u(as[r1 + 4], aH3, aL3);
                #pragma unroll
                for (int nf = 0; nf < 4; nf++) {
                    mma_tf32(acc[mf][nf], aH0, aH1, aH2, aH3, bHf[nf][0], bHf[nf][1]);
                    mma_tf32(acc[mf][nf], aL0, aL1, aL2, aL3, bHf[nf][0], bHf[nf][1]);
                }
            }
        }
        if (more) CP_WAIT0();
        __syncthreads();
        buf ^= 1;
    }

    #pragma unroll
    for (int mf = 0; mf < 4; mf++) {
        const int row = rowBase + wm + mf * 16 + g;
        #pragma unroll
        for (int nf = 0; nf < 4; nf++) {
            const int col = colBase + wn + nf * 8 + 2 * tg;
            const float b0 = bias[col];
            const float b1 = bias[col + 1];
            if (row < M) {
                float2 o0 = make_float2(acc[mf][nf][0] + b0, acc[mf][nf][1] + b1);
                *(float2*)(C + (size_t)row * EE + col) = o0;
            }
            if (row + 8 < M) {
                float2 o1 = make_float2(acc[mf][nf][2] + b0, acc[mf][nf][3] + b1);
                *(float2*)(C + (size_t)(row + 8) * EE + col) = o1;
            }
        }
    }
}

// ---------------------------------------------------------------------------
// Tensor-core flash attention (2xTF32), fp32 smem.
// K/V tiles pre-converted to tf32-hi in place (each thread converts its own
// cp.async chunks) so MMA B-operand loads are plain LDS with no per-warp cvt.
// Block: 128 q-rows; k-tiles of 64. 8 warps; warp w owns q rows [16w,16w+16).
// Dynamic smem: Qs[128][68] Ks[64][68] Vs[64][72] Ps[128][68]
//             = 26368 floats = 105472 B -> 2 CTAs/SM.
// ---------------------------------------------------------------------------
#define FQB 128
#define FKB 64
#define QS 68
#define KS 68
#define VS 72
#define PS 68
#define FSMEM_FLOATS (128*QS + 64*KS + 64*VS + 128*PS)   // 26368

__global__ __launch_bounds__(256, 2) void flash_attn_tc(
    const float* __restrict__ q, const float* __restrict__ k,
    const float* __restrict__ v, float* __restrict__ o)
{
    extern __shared__ float sm[];
    float* Qs = sm;
    float* Ks = Qs + 128 * QS;
    float* Vs = Ks + 64 * KS;
    float* Ps = Vs + 64 * VS;
    const uint32_t sQ = smem_u32(Qs);
    const uint32_t sK = smem_u32(Ks);
    const uint32_t sV = smem_u32(Vs);

    const int tid  = threadIdx.x;
    const int lane = tid & 31;
    const int wid  = tid >> 5;       // 0..7
    const int g    = lane >> 2;      // 0..7
    const int tg   = lane & 3;       // 0..3

    const int bh = blockIdx.x;
    const int b = bh >> 4;
    const int h = bh & 15;
    const int q0 = blockIdx.y * FQB;

    const size_t base = (size_t)b * TT * EE + (size_t)h * DD;
    const float* Q = q + base;
    const float* K = k + base;
    const float* V = v + base;
    float* O = o + base;

    // ---- stage Q tile via cp.async: 128 rows x 16 chunks = 2048 ----
    #pragma unroll
    for (int i = 0; i < 8; i++) {
        const int idx = tid + i * 256;
        const int r = idx >> 4;
        const int c4 = (idx & 15) << 2;
        const int gr = q0 + r;
        cp16(sQ + (uint32_t)(r * QS + c4) * 4, Q + (size_t)gr * EE + c4, gr < TT);
    }
    CP_COMMIT();

    float m0 = -1e30f, m1 = -1e30f, l0 = 0.f, l1 = 0.f;
    float oacc[8][4];
    #pragma unroll
    for (int nf = 0; nf < 8; nf++)
        #pragma unroll
        for (int c = 0; c < 4; c++) oacc[nf][c] = 0.f;

    const int row0 = 16 * wid + g;   // local q rows owned by this lane
    const int row1 = row0 + 8;

    const int nkt = (TT + FKB - 1) / FKB;   // 10
    for (int kt = 0; kt < nkt; kt++) {
        const int kbase = kt * FKB;
        __syncthreads();   // prev iter K/V readers done

        // ---- stage K,V tile: 64 rows x 16 chunks = 1024 each ----
        #pragma unroll
        for (int i = 0; i < 4; i++) {
            const int idx = tid + i * 256;
            const int r = idx >> 4;
            const int c4 = (idx & 15) << 2;
            const int gr = kbase + r;
            cp16(sK + (uint32_t)(r * KS + c4) * 4, K + (size_t)gr * EE + c4, gr < TT);
            cp16(sV + (uint32_t)(r * VS + c4) * 4, V + (size_t)gr * EE + c4, gr < TT);
        }
        CP_COMMIT();
        CP_WAIT0();          // also covers the Q group on iter 0

        // ---- convert OWN staged K/V chunks to tf32-hi in place ----
        // (each thread touches exactly the locations it staged; visibility to
        // other threads is published by the syncthreads below)
        #pragma unroll
        for (int i = 0; i < 4; i++) {
            const int idx = tid + i * 256;
            const int r = idx >> 4;
            const int c4 = (idx & 15) << 2;
            float4* kp = (float4*)&Ks[r * KS + c4];
            float4 kv = *kp;
            kv.x = tf32f(kv.x); kv.y = tf32f(kv.y);
            kv.z = tf32f(kv.z); kv.w = tf32f(kv.w);
            *kp = kv;
            float4* vp = (float4*)&Vs[r * VS + c4];
            float4 vv = *vp;
            vv.x = tf32f(vv.x); vv.y = tf32f(vv.y);
            vv.z = tf32f(vv.z); vv.w = tf32f(vv.w);
            *vp = vv;
        }
        __syncthreads();

        // ---- S = Q K^T (2xTF32), warp computes 16 rows x 64 keys ----
        float sacc[8][4];
        #pragma unroll
        for (int nf = 0; nf < 8; nf++)
            #pragma unroll
            for (int c = 0; c < 4; c++) sacc[nf][c] = 0.f;

        #pragma unroll
        for (int kd = 0; kd < 8; kd++) {
            const int ar0 = row0 * QS + kd * 8 + tg;
            const int ar1 = ar0 + 8 * QS;
            uint32_t aH0, aH1, aH2, aH3, aL0, aL1, aL2, aL3;
            split_u(Qs[ar0],     aH0, aL0);
            split_u(Qs[ar1],     aH1, aL1);
            split_u(Qs[ar0 + 4], aH2, aL2);
            split_u(Qs[ar1 + 4], aH3, aL3);
            #pragma unroll
            for (int nf = 0; nf < 8; nf++) {
                const int br = (8 * nf + g) * KS + kd * 8 + tg;
                const uint32_t bH0 = __float_as_uint(Ks[br]);
                const uint32_t bH1 = __float_as_uint(Ks[br + 4]);
                mma_tf32(sacc[nf], aH0, aH1, aH2, aH3, bH0, bH1);
                mma_tf32(sacc[nf], aL0, aL1, aL2, aL3, bH0, bH1);
            }
        }

        // ---- scale + mask + row max ----
        float mx0 = -1e30f, mx1 = -1e30f;
        #pragma unroll
        for (int nf = 0; nf < 8; nf++) {
            const int kc0 = kbase + 8 * nf + 2 * tg;
            const int kc1 = kc0 + 1;
            sacc[nf][0] = (kc0 < TT) ? sacc[nf][0] * 0.125f : -1e30f;
            sacc[nf][1] = (kc1 < TT) ? sacc[nf][1] * 0.125f : -1e30f;
            sacc[nf][2] = (kc0 < TT) ? sacc[nf][2] * 0.125f : -1e30f;
            sacc[nf][3] = (kc1 < TT) ? sacc[nf][3] * 0.125f : -1e30f;
            mx0 = fmaxf(mx0, fmaxf(sacc[nf][0], sacc[nf][1]));
            mx1 = fmaxf(mx1, fmaxf(sacc[nf][2], sacc[nf][3]));
        }
        mx0 = fmaxf(mx0, __shfl_xor_sync(0xffffffffu, mx0, 1));
        mx0 = fmaxf(mx0, __shfl_xor_sync(0xffffffffu, mx0, 2));
        mx1 = fmaxf(mx1, __shfl_xor_sync(0xffffffffu, mx1, 1));
        mx1 = fmaxf(mx1, __shfl_xor_sync(0xffffffffu, mx1, 2));

        const float mn0 = fmaxf(m0, mx0);
        const float mn1 = fmaxf(m1, mx1);
        const float cc0 = __expf(m0 - mn0);
        const float cc1 = __expf(m1 - mn1);
        m0 = mn0; m1 = mn1;

        // ---- P = exp(s - m): store fp32 to smem, accumulate row sums ----
        float rs0 = 0.f, rs1 = 0.f;
        #pragma unroll
        for (int nf = 0; nf < 8; nf++) {
            const float p0 = __expf(sacc[nf][0] - m0);
            const float p1 = __expf(sacc[nf][1] - m0);
            const float p2 = __expf(sacc[nf][2] - m1);
            const float p3 = __expf(sacc[nf][3] - m1);
            rs0 += p0 + p1;
            rs1 += p2 + p3;
            const int col = 8 * nf + 2 * tg;
            *(float2*)&Ps[row0 * PS + col] = make_float2(p0, p1);
            *(float2*)&Ps[row1 * PS + col] = make_float2(p2, p3);
        }
        rs0 += __shfl_xor_sync(0xffffffffu, rs0, 1);
        rs0 += __shfl_xor_sync(0xffffffffu, rs0, 2);
        rs1 += __shfl_xor_sync(0xffffffffu, rs1, 1);
        rs1 += __shfl_xor_sync(0xffffffffu, rs1, 2);
        l0 = l0 * cc0 + rs0;
        l1 = l1 * cc1 + rs1;

        #pragma unroll
        for (int nf = 0; nf < 8; nf++) {
            oacc[nf][0] *= cc0;
            oacc[nf][1] *= cc0;
            oacc[nf][2] *= cc1;
            oacc[nf][3] *= cc1;
        }
        __syncwarp();   // P rows are warp-private: cross-lane visibility

        // ---- O += P V (2xTF32) ----
        #pragma unroll
        for (int kc = 0; kc < 8; kc++) {
            const int ar0 = row0 * PS + kc * 8 + tg;
            const int ar1 = ar0 + 8 * PS;
            uint32_t aH0, aH1, aH2, aH3, aL0, aL1, aL2, aL3;
            split_u(Ps[ar0],     aH0, aL0);
            split_u(Ps[ar1],     aH1, aL1);
            split_u(Ps[ar0 + 4], aH2, aL2);
            split_u(Ps[ar1 + 4], aH3, aL3);
            #pragma unroll
            for (int nfd = 0; nfd < 8; nfd++) {
                const int br0 = (kc * 8 + tg) * VS + nfd * 8 + g;
                const int br1 = br0 + 4 * VS;
                const uint32_t bH0 = __float_as_uint(Vs[br0]);
                const uint32_t bH1 = __float_as_uint(Vs[br1]);
                mma_tf32(oacc[nfd], aH0, aH1, aH2, aH3, bH0, bH1);
                mma_tf32(oacc[nfd], aL0, aL1, aL2, aL3, bH0, bH1);
            }
        }
    }

    // ---- epilogue: normalize + store ----
    const float inv0 = 1.f / l0;
    const float inv1 = 1.f / l1;
    const int gr0 = q0 + row0;
    const int gr1 = q0 + row1;
    #pragma unroll
    for (int nfd = 0; nfd < 8; nfd++) {
        const int col = nfd * 8 + 2 * tg;
        if (gr0 < TT)
            *(float2*)(O + (size_t)gr0 * EE + col) =
                make_float2(oacc[nfd][0] * inv0, oacc[nfd][1] * inv0);
        if (gr1 < TT)
            *(float2*)(O + (size_t)gr1 * EE + col) =
                make_float2(oacc[nfd][2] * inv1, oacc[nfd][3] * inv1);
    }
}

// ---------------------------------------------------------------------------
// Launch
// ---------------------------------------------------------------------------
extern "C" void kernel_launch(void* const* d_in, const int* in_sizes, int n_in,
                              void* d_out, int out_size)
{
    const float* x  = (const float*)d_in[0];
    const float* Wq = (const float*)d_in[1];
    const float* bq = (const float*)d_in[2];
    const float* Wk = (const float*)d_in[3];
    const float* bk = (const float*)d_in[4];
    const float* Wv = (const float*)d_in[5];
    const float* bv = (const float*)d_in[6];
    const float* Wo = (const float*)d_in[7];
    const float* bo = (const float*)d_in[8];
    float* out = (float*)d_out;

    float *gq, *gk, *gv, *ga;
    cudaGetSymbolAddress((void**)&gq, g_q);
    cudaGetSymbolAddress((void**)&gk, g_k);
    cudaGetSymbolAddress((void**)&gv, g_v);
    cudaGetSymbolAddress((void**)&ga, g_att);

    const int smemG = GSMEM_FLOATS * 4;   // 104448
    const int smemF = FSMEM_FLOATS * 4;   // 105472
    cudaFuncSetAttribute(gemm_tf32x2, cudaFuncAttributeMaxDynamicSharedMemorySize, smemG);
    cudaFuncSetAttribute(flash_attn_tc, cudaFuncAttributeMaxDynamicSharedMemorySize, smemF);

    dim3 gridG(EE / GBN, (MM + 127) / 128);   // (4, 145)
    gemm_tf32x2<<<gridG, 512, smemG>>>(x, Wq, bq, gq, MM);
    gemm_tf32x2<<<gridG, 512, smemG>>>(x, Wk, bk, gk, MM);
    gemm_tf32x2<<<gridG, 512, smemG>>>(x, Wv, bv, gv, MM);

    dim3 gridA(BB * HH, (TT + FQB - 1) / FQB);  // (512, 5)
    flash_attn_tc<<<gridA, 256, smemF>>>(gq, gk, gv, ga);

    gemm_tf32x2<<<gridG, 512, smemG>>>(ga, Wo, bo, out, MM);
}

// round 11
// speedup vs baseline: 1.1014x; 1.1014x over previous
#include <cuda_runtime.h>
#include <cuda_bf16.h>
#include <math.h>
#include <stdint.h>

// Problem constants
#define BB 32
#define TT 577
#define EE 1024
#define HH 16
#define DD 64
#define MM (BB * TT)   // 18464 rows

// Scratch (alloc-free rule: __device__ globals)
__device__ float g_q[(size_t)MM * EE];
__device__ float g_k[(size_t)MM * EE];
__device__ float g_v[(size_t)MM * EE];
__device__ float g_att[(size_t)MM * EE];

// ---------------------------------------------------------------------------
// helpers
// ---------------------------------------------------------------------------
// 2-op split: hi = tf32_rna(x); lo = x - hi as raw fp32 bits (lo rides RZ).
__device__ __forceinline__ void split_u(float x, uint32_t& hi, uint32_t& lo) {
    uint32_t uh;
    asm("cvt.rna.tf32.f32 %0, %1;" : "=r"(uh) : "f"(x));
    hi = uh;
    lo = __float_as_uint(x - __uint_as_float(uh));
}

// hi-only convert for B operands (2xTF32: a*b ~= aH*bH + aL*bH)
__device__ __forceinline__ uint32_t cvt_hi(float x) {
    uint32_t uh;
    asm("cvt.rna.tf32.f32 %0, %1;" : "=r"(uh) : "f"(x));
    return uh;
}
__device__ __forceinline__ float tf32f(float x) {
    uint32_t u;
    asm("cvt.rna.tf32.f32 %0, %1;" : "=r"(u) : "f"(x));
    return __uint_as_float(u);
}

__device__ __forceinline__ void mma_tf32(float* acc,
                                         uint32_t a0, uint32_t a1, uint32_t a2, uint32_t a3,
                                         uint32_t b0, uint32_t b1) {
    asm volatile(
        "mma.sync.aligned.m16n8k8.row.col.f32.tf32.tf32.f32 "
        "{%0,%1,%2,%3}, {%4,%5,%6,%7}, {%8,%9}, {%0,%1,%2,%3};\n"
        : "+f"(acc[0]), "+f"(acc[1]), "+f"(acc[2]), "+f"(acc[3])
        : "r"(a0), "r"(a1), "r"(a2), "r"(a3), "r"(b0), "r"(b1));
}

__device__ __forceinline__ uint32_t smem_u32(const void* p) {
    return (uint32_t)__cvta_generic_to_shared(p);
}

// cp.async 16B with zero-fill when pred is false (src not accessed)
__device__ __forceinline__ void cp16(uint32_t dst, const void* src, bool pred) {
    asm volatile("cp.async.cg.shared.global [%0], [%1], 16, %2;\n"
                 :: "r"(dst), "l"(src), "r"(pred ? 16 : 0));
}
#define CP_COMMIT() asm volatile("cp.async.commit_group;\n" ::: "memory")
#define CP_WAIT0()  asm volatile("cp.async.wait_group 0;\n" ::: "memory")

// ---------------------------------------------------------------------------
// GEMM (2xTF32): C[M,1024] = A[M,1024] @ B[1024,1024] + bias
// Block tile 128x256, BK=32, 8 warps (2x4), warp tile 64x64, 256 threads.
// Per-ks: ALL A frags preloaded+split (32 regs), then B frags, then 128 MMAs
// (concentrates LDS latency where the previous ks's MMA drain covers it).
// Dynamic smem: AS[2][128][36] + BS[2][32][264] = 104448 B. 1 CTA/SM.
// ---------------------------------------------------------------------------
#define GBN 256
#define GA_STRIDE 36
#define GB_STRIDE 264
#define GA_BUF (128 * GA_STRIDE)   // 4608 floats
#define GB_BUF (32 * GB_STRIDE)    // 8448 floats
#define GSMEM_FLOATS (2 * (GA_BUF + GB_BUF))   // 26112

__global__ __launch_bounds__(256, 1) void gemm_tf32x2(
    const float* __restrict__ A, const float* __restrict__ B,
    const float* __restrict__ bias, float* __restrict__ C, int M)
{
    extern __shared__ float sm[];
    float* AS = sm;                   // [2][128][36]
    float* BS = AS + 2 * GA_BUF;      // [2][32][264]
    const uint32_t sA = smem_u32(AS);
    const uint32_t sB = smem_u32(BS);

    const int tid  = threadIdx.x;
    const int lane = tid & 31;
    const int wid  = tid >> 5;        // 0..7
    const int g    = lane >> 2;       // 0..7
    const int tg   = lane & 3;        // 0..3
    const int wm   = (wid >> 2) * 64; // warp row offset (0/64)
    const int wn   = (wid & 3) * 64;  // warp col offset (0/64/128/192)
    const int rowBase = blockIdx.y * 128;
    const int colBase = blockIdx.x * GBN;

    float acc[4][8][4];
    #pragma unroll
    for (int mf = 0; mf < 4; mf++)
        #pragma unroll
        for (int nf = 0; nf < 8; nf++)
            #pragma unroll
            for (int c = 0; c < 4; c++) acc[mf][nf][c] = 0.f;

    auto issue = [&](int buf, int k0) {
        // A tile: 128 rows x 8 chunks = 1024
        #pragma unroll
        for (int i = 0; i < 4; i++) {
            const int idx = tid + i * 256;
            const int r = idx >> 3;
            const int c4 = (idx & 7) * 4;
            const int gr = rowBase + r;
            cp16(sA + (uint32_t)(buf * GA_BUF + r * GA_STRIDE + c4) * 4,
                 A + (size_t)gr * EE + k0 + c4, gr < M);
        }
        // B tile: 32 rows x 64 chunks = 2048
        #pragma unroll
        for (int i = 0; i < 8; i++) {
            const int idx = tid + i * 256;
            const int r = idx >> 6;
            const int c4 = (idx & 63) * 4;
            cp16(sB + (uint32_t)(buf * GB_BUF + r * GB_STRIDE + c4) * 4,
                 B + (size_t)(k0 + r) * EE + colBase + c4, true);
        }
        CP_COMMIT();
    };

    issue(0, 0);
    CP_WAIT0();
    __syncthreads();

    int buf = 0;
    for (int k0 = 0; k0 < EE; k0 += 32) {
        const bool more = (k0 + 32 < EE);
        if (more) issue(buf ^ 1, k0 + 32);   // DMA overlaps compute below

        const float* as = AS + buf * GA_BUF;
        const float* bs = BS + buf * GB_BUF;

        #pragma unroll
        for (int ks = 0; ks < 4; ks++) {
            // ---- preload ALL A fragments for this ks (4 mf groups) ----
            uint32_t aH[4][4], aL[4][4];
            #pragma unroll
            for (int mf = 0; mf < 4; mf++) {
                const int r0 = (wm + mf * 16 + g) * GA_STRIDE + ks * 8 + tg;
                const int r1 = r0 + 8 * GA_STRIDE;
                split_u(as[r0],     aH[mf][0], aL[mf][0]);
                split_u(as[r1],     aH[mf][1], aL[mf][1]);
                split_u(as[r0 + 4], aH[mf][2], aL[mf][2]);
                split_u(as[r1 + 4], aH[mf][3], aL[mf][3]);
            }
            // ---- B fragments ----
            uint32_t bHf[8][2];
            const int br0 = (ks * 8 + tg) * GB_STRIDE;
            const int br1 = br0 + 4 * GB_STRIDE;
            #pragma unroll
            for (int nf = 0; nf < 8; nf++) {
                const int col = wn + nf * 8 + g;
                bHf[nf][0] = cvt_hi(bs[br0 + col]);
                bHf[nf][1] = cvt_hi(bs[br1 + col]);
            }
            // ---- 128 MMAs, no internal memory stalls ----
            #pragma unroll
            for (int mf = 0; mf < 4; mf++) {
                #pragma unroll
                for (int nf = 0; nf < 8; nf++) {
                    mma_tf32(acc[mf][nf], aH[mf][0], aH[mf][1], aH[mf][2], aH[mf][3],
                             bHf[nf][0], bHf[nf][1]);
                    mma_tf32(acc[mf][nf], aL[mf][0], aL[mf][1], aL[mf][2], aL[mf][3],
                             bHf[nf][0], bHf[nf][1]);
                }
            }
        }
        if (more) CP_WAIT0();
        __syncthreads();
        buf ^= 1;
    }

    #pragma unroll
    for (int mf = 0; mf < 4; mf++) {
        const int row = rowBase + wm + mf * 16 + g;
        #pragma unroll
        for (int nf = 0; nf < 8; nf++) {
            const int col = colBase + wn + nf * 8 + 2 * tg;
            const float b0 = bias[col];
            const float b1 = bias[col + 1];
            if (row < M) {
                float2 o0 = make_float2(acc[mf][nf][0] + b0, acc[mf][nf][1] + b1);
                *(float2*)(C + (size_t)row * EE + col) = o0;
            }
            if (row + 8 < M) {
                float2 o1 = make_float2(acc[mf][nf][2] + b0, acc[mf][nf][3] + b1);
                *(float2*)(C + (size_t)(row + 8) * EE + col) = o1;
            }
        }
    }
}

// ---------------------------------------------------------------------------
// Tensor-core flash attention (2xTF32), fp32 smem.
// K/V tiles pre-converted to tf32-hi in place (each thread converts its own
// cp.async chunks) so MMA B-operand loads are plain LDS with no per-warp cvt.
// Block: 128 q-rows; k-tiles of 64. 8 warps; warp w owns q rows [16w,16w+16).
// Dynamic smem: Qs[128][68] Ks[64][68] Vs[64][72] Ps[128][68]
//             = 26368 floats = 105472 B -> 2 CTAs/SM.
// ---------------------------------------------------------------------------
#define FQB 128
#define FKB 64
#define QS 68
#define KS 68
#define VS 72
#define PS 68
#define FSMEM_FLOATS (128*QS + 64*KS + 64*VS + 128*PS)   // 26368

__global__ __launch_bounds__(256, 2) void flash_attn_tc(
    const float* __restrict__ q, const float* __restrict__ k,
    const float* __restrict__ v, float* __restrict__ o)
{
    extern __shared__ float sm[];
    float* Qs = sm;
    float* Ks = Qs + 128 * QS;
    float* Vs = Ks + 64 * KS;
    float* Ps = Vs + 64 * VS;
    const uint32_t sQ = smem_u32(Qs);
    const uint32_t sK = smem_u32(Ks);
    const uint32_t sV = smem_u32(Vs);

    const int tid  = threadIdx.x;
    const int lane = tid & 31;
    const int wid  = tid >> 5;       // 0..7
    const int g    = lane >> 2;      // 0..7
    const int tg   = lane & 3;       // 0..3

    const int bh = blockIdx.x;
    const int b = bh >> 4;
    const int h = bh & 15;
    const int q0 = blockIdx.y * FQB;

    const size_t base = (size_t)b * TT * EE + (size_t)h * DD;
    const float* Q = q + base;
    const float* K = k + base;
    const float* V = v + base;
    float* O = o + base;

    // ---- stage Q tile via cp.async: 128 rows x 16 chunks = 2048 ----
    #pragma unroll
    for (int i = 0; i < 8; i++) {
        const int idx = tid + i * 256;
        const int r = idx >> 4;
        const int c4 = (idx & 15) << 2;
        const int gr = q0 + r;
        cp16(sQ + (uint32_t)(r * QS + c4) * 4, Q + (size_t)gr * EE + c4, gr < TT);
    }
    CP_COMMIT();

    float m0 = -1e30f, m1 = -1e30f, l0 = 0.f, l1 = 0.f;
    float oacc[8][4];
    #pragma unroll
    for (int nf = 0; nf < 8; nf++)
        #pragma unroll
        for (int c = 0; c < 4; c++) oacc[nf][c] = 0.f;

    const int row0 = 16 * wid + g;   // local q rows owned by this lane
    const int row1 = row0 + 8;

    const int nkt = (TT + FKB - 1) / FKB;   // 10
    for (int kt = 0; kt < nkt; kt++) {
        const int kbase = kt * FKB;
        __syncthreads();   // prev iter K/V readers done

        // ---- stage K,V tile: 64 rows x 16 chunks = 1024 each ----
        #pragma unroll
        for (int i = 0; i < 4; i++) {
            const int idx = tid + i * 256;
            const int r = idx >> 4;
            const int c4 = (idx & 15) << 2;
            const int gr = kbase + r;
            cp16(sK + (uint32_t)(r * KS + c4) * 4, K + (size_t)gr * EE + c4, gr < TT);
            cp16(sV + (uint32_t)(r * VS + c4) * 4, V + (size_t)gr * EE + c4, gr < TT);
        }
        CP_COMMIT();
        CP_WAIT0();          // also covers the Q group on iter 0

        // ---- convert OWN staged K/V chunks to tf32-hi in place ----
        #pragma unroll
        for (int i = 0; i < 4; i++) {
            const int idx = tid + i * 256;
            const int r = idx >> 4;
            const int c4 = (idx & 15) << 2;
            float4* kp = (float4*)&Ks[r * KS + c4];
            float4 kv = *kp;
            kv.x = tf32f(kv.x); kv.y = tf32f(kv.y);
            kv.z = tf32f(kv.z); kv.w = tf32f(kv.w);
            *kp = kv;
            float4* vp = (float4*)&Vs[r * VS + c4];
            float4 vv = *vp;
            vv.x = tf32f(vv.x); vv.y = tf32f(vv.y);
            vv.z = tf32f(vv.z); vv.w = tf32f(vv.w);
            *vp = vv;
        }
        __syncthreads();

        // ---- S = Q K^T (2xTF32), warp computes 16 rows x 64 keys ----
        float sacc[8][4];
        #pragma unroll
        for (int nf = 0; nf < 8; nf++)
            #pragma unroll
            for (int c = 0; c < 4; c++) sacc[nf][c] = 0.f;

        #pragma unroll
        for (int kd = 0; kd < 8; kd++) {
            const int ar0 = row0 * QS + kd * 8 + tg;
            const int ar1 = ar0 + 8 * QS;
            uint32_t aH0, aH1, aH2, aH3, aL0, aL1, aL2, aL3;
            split_u(Qs[ar0],     aH0, aL0);
            split_u(Qs[ar1],     aH1, aL1);
            split_u(Qs[ar0 + 4], aH2, aL2);
            split_u(Qs[ar1 + 4], aH3, aL3);
            #pragma unroll
            for (int nf = 0; nf < 8; nf++) {
                const int br = (8 * nf + g) * KS + kd * 8 + tg;
                const uint32_t bH0 = __float_as_uint(Ks[br]);
                const uint32_t bH1 = __float_as_uint(Ks[br + 4]);
                mma_tf32(sacc[nf], aH0, aH1, aH2, aH3, bH0, bH1);
                mma_tf32(sacc[nf], aL0, aL1, aL2, aL3, bH0, bH1);
            }
        }

        // ---- scale + mask + row max ----
        float mx0 = -1e30f, mx1 = -1e30f;
        #pragma unroll
        for (int nf = 0; nf < 8; nf++) {
            const int kc0 = kbase + 8 * nf + 2 * tg;
            const int kc1 = kc0 + 1;
            sacc[nf][0] = (kc0 < TT) ? sacc[nf][0] * 0.125f : -1e30f;
            sacc[nf][1] = (kc1 < TT) ? sacc[nf][1] * 0.125f : -1e30f;
            sacc[nf][2] = (kc0 < TT) ? sacc[nf][2] * 0.125f : -1e30f;
            sacc[nf][3] = (kc1 < TT) ? sacc[nf][3] * 0.125f : -1e30f;
            mx0 = fmaxf(mx0, fmaxf(sacc[nf][0], sacc[nf][1]));
            mx1 = fmaxf(mx1, fmaxf(sacc[nf][2], sacc[nf][3]));
        }
        mx0 = fmaxf(mx0, __shfl_xor_sync(0xffffffffu, mx0, 1));
        mx0 = fmaxf(mx0, __shfl_xor_sync(0xffffffffu, mx0, 2));
        mx1 = fmaxf(mx1, __shfl_xor_sync(0xffffffffu, mx1, 1));
        mx1 = fmaxf(mx1, __shfl_xor_sync(0xffffffffu, mx1, 2));

        const float mn0 = fmaxf(m0, mx0);
        const float mn1 = fmaxf(m1, mx1);
        const float cc0 = __expf(m0 - mn0);
        const float cc1 = __expf(m1 - mn1);
        m0 = mn0; m1 = mn1;

        // ---- P = exp(s - m): store fp32 to smem, accumulate row sums ----
        float rs0 = 0.f, rs1 = 0.f;
        #pragma unroll
        for (int nf = 0; nf < 8; nf++) {
            const float p0 = __expf(sacc[nf][0] - m0);
            const float p1 = __expf(sacc[nf][1] - m0);
            const float p2 = __expf(sacc[nf][2] - m1);
            const float p3 = __expf(sacc[nf][3] - m1);
            rs0 += p0 + p1;
            rs1 += p2 + p3;
            const int col = 8 * nf + 2 * tg;
            *(float2*)&Ps[row0 * PS + col] = make_float2(p0, p1);
            *(float2*)&Ps[row1 * PS + col] = make_float2(p2, p3);
        }
        rs0 += __shfl_xor_sync(0xffffffffu, rs0, 1);
        rs0 += __shfl_xor_sync(0xffffffffu, rs0, 2);
        rs1 += __shfl_xor_sync(0xffffffffu, rs1, 1);
        rs1 += __shfl_xor_sync(0xffffffffu, rs1, 2);
        l0 = l0 * cc0 + rs0;
        l1 = l1 * cc1 + rs1;

        #pragma unroll
        for (int nf = 0; nf < 8; nf++) {
            oacc[nf][0] *= cc0;
            oacc[nf][1] *= cc0;
            oacc[nf][2] *= cc1;
            oacc[nf][3] *= cc1;
        }
        __syncwarp();   // P rows are warp-private: cross-lane visibility

        // ---- O += P V (2xTF32) ----
        #pragma unroll
        for (int kc = 0; kc < 8; kc++) {
            const int ar0 = row0 * PS + kc * 8 + tg;
            const int ar1 = ar0 + 8 * PS;
            uint32_t aH0, aH1, aH2, aH3, aL0, aL1, aL2, aL3;
            split_u(Ps[ar0],     aH0, aL0);
            split_u(Ps[ar1],     aH1, aL1);
            split_u(Ps[ar0 + 4], aH2, aL2);
            split_u(Ps[ar1 + 4], aH3, aL3);
            #pragma unroll
            for (int nfd = 0; nfd < 8; nfd++) {
                const int br0 = (kc * 8 + tg) * VS + nfd * 8 + g;
                const int br1 = br0 + 4 * VS;
                const uint32_t bH0 = __float_as_uint(Vs[br0]);
                const uint32_t bH1 = __float_as_uint(Vs[br1]);
                mma_tf32(oacc[nfd], aH0, aH1, aH2, aH3, bH0, bH1);
                mma_tf32(oacc[nfd], aL0, aL1, aL2, aL3, bH0, bH1);
            }
        }
    }

    // ---- epilogue: normalize + store ----
    const float inv0 = 1.f / l0;
    const float inv1 = 1.f / l1;
    const int gr0 = q0 + row0;
    const int gr1 = q0 + row1;
    #pragma unroll
    for (int nfd = 0; nfd < 8; nfd++) {
        const int col = nfd * 8 + 2 * tg;
        if (gr0 < TT)
            *(float2*)(O + (size_t)gr0 * EE + col) =
                make_float2(oacc[nfd][0] * inv0, oacc[nfd][1] * inv0);
        if (gr1 < TT)
            *(float2*)(O + (size_t)gr1 * EE + col) =
                make_float2(oacc[nfd][2] * inv1, oacc[nfd][3] * inv1);
    }
}

// ---------------------------------------------------------------------------
// Launch
// ---------------------------------------------------------------------------
extern "C" void kernel_launch(void* const* d_in, const int* in_sizes, int n_in,
                              void* d_out, int out_size)
{
    const float* x  = (const float*)d_in[0];
    const float* Wq = (const float*)d_in[1];
    const float* bq = (const float*)d_in[2];
    const float* Wk = (const float*)d_in[3];
    const float* bk = (const float*)d_in[4];
    const float* Wv = (const float*)d_in[5];
    const float* bv = (const float*)d_in[6];
    const float* Wo = (const float*)d_in[7];
    const float* bo = (const float*)d_in[8];
    float* out = (float*)d_out;

    float *gq, *gk, *gv, *ga;
    cudaGetSymbolAddress((void**)&gq, g_q);
    cudaGetSymbolAddress((void**)&gk, g_k);
    cudaGetSymbolAddress((void**)&gv, g_v);
    cudaGetSymbolAddress((void**)&ga, g_att);

    const int smemG = GSMEM_FLOATS * 4;   // 104448
    const int smemF = FSMEM_FLOATS * 4;   // 105472
    cudaFuncSetAttribute(gemm_tf32x2, cudaFuncAttributeMaxDynamicSharedMemorySize, smemG);
    cudaFuncSetAttribute(flash_attn_tc, cudaFuncAttributeMaxDynamicSharedMemorySize, smemF);

    dim3 gridG(EE / GBN, (MM + 127) / 128);   // (4, 145)
    gemm_tf32x2<<<gridG, 256, smemG>>>(x, Wq, bq, gq, MM);
    gemm_tf32x2<<<gridG, 256, smemG>>>(x, Wk, bk, gk, MM);
    gemm_tf32x2<<<gridG, 256, smemG>>>(x, Wv, bv, gv, MM);

    dim3 gridA(BB * HH, (TT + FQB - 1) / FQB);  // (512, 5)
    flash_attn_tc<<<gridA, 256, smemF>>>(gq, gk, gv, ga);

    gemm_tf32x2<<<gridG, 256, smemG>>>(ga, Wo, bo, out, MM);
}

// round 14
// speedup vs baseline: 1.2166x; 1.1046x over previous
#include <cuda_runtime.h>
#include <cuda_bf16.h>
#include <math.h>
#include <stdint.h>

// Problem constants
#define BB 32
#define TT 577
#define EE 1024
#define HH 16
#define DD 64
#define MM (BB * TT)   // 18464 rows

// Scratch (alloc-free rule: __device__ globals)
__device__ float g_q[(size_t)MM * EE];
__device__ float g_k[(size_t)MM * EE];
__device__ float g_v[(size_t)MM * EE];
__device__ __nv_bfloat16 g_xh[(size_t)MM * EE];
__device__ __nv_bfloat16 g_xl[(size_t)MM * EE];
__device__ __nv_bfloat16 g_ah[(size_t)MM * EE];
__device__ __nv_bfloat16 g_al[(size_t)MM * EE];
__device__ __nv_bfloat16 g_wth[(size_t)4 * EE * EE];   // W^T hi, [n][k]
__device__ __nv_bfloat16 g_wtl[(size_t)4 * EE * EE];   // W^T lo

// ---------------------------------------------------------------------------
// common helpers
// ---------------------------------------------------------------------------
__device__ __forceinline__ uint32_t smem_u32(const void* p) {
    return (uint32_t)__cvta_generic_to_shared(p);
}
__device__ __forceinline__ void cp16(uint32_t dst, const void* src, bool pred) {
    asm volatile("cp.async.cg.shared.global [%0], [%1], 16, %2;\n"
                 :: "r"(dst), "l"(src), "r"(pred ? 16 : 0));
}
#define CP_COMMIT() asm volatile("cp.async.commit_group;\n" ::: "memory")
#define CP_WAIT0()  asm volatile("cp.async.wait_group 0;\n" ::: "memory")

// pack_bf16(a, b) -> u32 with mem order [bf16(a), bf16(b)]
__device__ __forceinline__ uint32_t pack_bf16(float lo, float hi) {
    uint32_t r;
    asm("cvt.rn.bf16x2.f32 %0, %1, %2;" : "=r"(r) : "f"(hi), "f"(lo));
    return r;
}
__device__ __forceinline__ float bf16lo_f(uint32_t p) { return __uint_as_float(p << 16); }
__device__ __forceinline__ float bf16hi_f(uint32_t p) { return __uint_as_float(p & 0xffff0000u); }

// tf32 helpers (flash attention, unchanged math)
__device__ __forceinline__ void split_u(float x, uint32_t& hi, uint32_t& lo) {
    uint32_t uh;
    asm("cvt.rna.tf32.f32 %0, %1;" : "=r"(uh) : "f"(x));
    hi = uh;
    lo = __float_as_uint(x - __uint_as_float(uh));
}
__device__ __forceinline__ float tf32f(float x) {
    uint32_t u;
    asm("cvt.rna.tf32.f32 %0, %1;" : "=r"(u) : "f"(x));
    return __uint_as_float(u);
}
__device__ __forceinline__ void mma_tf32(float* acc,
                                         uint32_t a0, uint32_t a1, uint32_t a2, uint32_t a3,
                                         uint32_t b0, uint32_t b1) {
    asm volatile(
        "mma.sync.aligned.m16n8k8.row.col.f32.tf32.tf32.f32 "
        "{%0,%1,%2,%3}, {%4,%5,%6,%7}, {%8,%9}, {%0,%1,%2,%3};\n"
        : "+f"(acc[0]), "+f"(acc[1]), "+f"(acc[2]), "+f"(acc[3])
        : "r"(a0), "r"(a1), "r"(a2), "r"(a3), "r"(b0), "r"(b1));
}

// bf16 m16n8k16 MMA (A row-major, B col-major i.e. [N][K])
__device__ __forceinline__ void mma_bf16(float* acc,
                                         uint32_t a0, uint32_t a1, uint32_t a2, uint32_t a3,
                                         uint32_t b0, uint32_t b1) {
    asm volatile(
        "mma.sync.aligned.m16n8k16.row.col.f32.bf16.bf16.f32 "
        "{%0,%1,%2,%3}, {%4,%5,%6,%7}, {%8,%9}, {%0,%1,%2,%3};\n"
        : "+f"(acc[0]), "+f"(acc[1]), "+f"(acc[2]), "+f"(acc[3])
        : "r"(a0), "r"(a1), "r"(a2), "r"(a3), "r"(b0), "r"(b1));
}

// ---------------------------------------------------------------------------
// prep kernels: fp32 -> bf16 hi/lo splits
// ---------------------------------------------------------------------------
__global__ void prep_x(const float* __restrict__ x,
                       __nv_bfloat16* __restrict__ xh,
                       __nv_bfloat16* __restrict__ xl, int n4) {
    int idx = blockIdx.x * 256 + threadIdx.x;
    if (idx >= n4) return;
    float4 v = ((const float4*)x)[idx];
    uint32_t h0 = pack_bf16(v.x, v.y);
    uint32_t h1 = pack_bf16(v.z, v.w);
    uint32_t l0 = pack_bf16(v.x - bf16lo_f(h0), v.y - bf16hi_f(h0));
    uint32_t l1 = pack_bf16(v.z - bf16lo_f(h1), v.w - bf16hi_f(h1));
    ((uint2*)xh)[idx] = make_uint2(h0, h1);
    ((uint2*)xl)[idx] = make_uint2(l0, l1);
}

// transpose + split: W[k][n] fp32 -> Wt_h/Wt_l [n][k] bf16 (64x64 tiles)
// NOTE: stride 68 (272 B = 17*16) keeps the float4 staging stores 16B-aligned
// (stride 65 was the R13 misaligned-address bug).
__global__ __launch_bounds__(256) void prep_w(const float* __restrict__ W,
                                              __nv_bfloat16* __restrict__ wth,
                                              __nv_bfloat16* __restrict__ wtl) {
    __shared__ float s[64][68];
    const int tid = threadIdx.x;
    const int k0 = blockIdx.y * 64, n0 = blockIdx.x * 64;
    #pragma unroll
    for (int i = 0; i < 4; i++) {
        const int idx = tid + i * 256;
        const int kk = idx >> 4;
        const int n4 = (idx & 15) * 4;
        *(float4*)&s[kk][n4] = *(const float4*)(W + (size_t)(k0 + kk) * EE + n0 + n4);
    }
    __syncthreads();
    #pragma unroll
    for (int i = 0; i < 4; i++) {
        const int idx = tid + i * 256;
        const int nn = idx >> 4;
        const int k4 = (idx & 15) * 4;
        float s0 = s[k4 + 0][nn], s1 = s[k4 + 1][nn];
        float s2 = s[k4 + 2][nn], s3 = s[k4 + 3][nn];
        uint32_t h0 = pack_bf16(s0, s1), h1 = pack_bf16(s2, s3);
        uint32_t l0 = pack_bf16(s0 - bf16lo_f(h0), s1 - bf16hi_f(h0));
        uint32_t l1 = pack_bf16(s2 - bf16lo_f(h1), s3 - bf16hi_f(h1));
        const size_t off = (size_t)(n0 + nn) * EE + k0 + k4;
        *(uint2*)(wth + off) = make_uint2(h0, h1);
        *(uint2*)(wtl + off) = make_uint2(l0, l1);
    }
}

// ---------------------------------------------------------------------------
// GEMM (3xBF16, mma.sync m16n8k16): C[M,1024] = A @ W + bias
// A: bf16 hi/lo [M][K]; B: bf16 hi/lo [N][K] (pre-transposed W).
// Block tile 128x256, BK=32 elems, 8 warps (2x4), warp tile 64x64.
// smem: packed bf16 (u32), row stride 20 u32 (banks 20g+tg all distinct).
// Per k0=32: 192 MMA + 128 LDS.32, zero cvt. Double-buffered cp.async.
// smem total: 2 * (2*2560 + 2*5120) u32 = 122880 B. 1 CTA/SM.
// ---------------------------------------------------------------------------
#define GBN 256
#define GKA 2560     // u32 per A hi/lo buffer (128 rows x 20)
#define GKB 5120     // u32 per B hi/lo buffer (256 rows x 20)
#define GBUF (2 * GKA + 2 * GKB)   // 15360 u32 per stage
#define GSMEM_B (2 * GBUF * 4)     // 122880 bytes

__global__ __launch_bounds__(256, 1) void gemm_bf16x3(
    const __nv_bfloat16* __restrict__ agh, const __nv_bfloat16* __restrict__ agl,
    const __nv_bfloat16* __restrict__ bgh, const __nv_bfloat16* __restrict__ bgl,
    const float* __restrict__ bias, float* __restrict__ C, int M)
{
    extern __shared__ uint32_t su[];
    const uint32_t sbase = smem_u32(su);

    const int tid  = threadIdx.x;
    const int lane = tid & 31;
    const int wid  = tid >> 5;        // 0..7
    const int g    = lane >> 2;       // 0..7
    const int tg   = lane & 3;        // 0..3
    const int wm   = (wid >> 2) * 64; // warp row offset (0/64)
    const int wn   = (wid & 3) * 64;  // warp col offset (0/64/128/192)
    const int rowBase = blockIdx.y * 128;
    const int colBase = blockIdx.x * GBN;

    float acc[4][8][4];
    #pragma unroll
    for (int mf = 0; mf < 4; mf++)
        #pragma unroll
        for (int nf = 0; nf < 8; nf++)
            #pragma unroll
            for (int c = 0; c < 4; c++) acc[mf][nf][c] = 0.f;

    auto stage = [&](int buf, int k0) {   // k0 in bf16 elements
        const uint32_t b0 = sbase + (uint32_t)buf * GBUF * 4;
        // A: 128 rows x 4 chunks (16B = 8 bf16) each for hi and lo
        #pragma unroll
        for (int i = 0; i < 2; i++) {
            const int idx = tid + i * 256;
            const int r = idx >> 2;
            const int c = idx & 3;
            const bool pred = (rowBase + r) < M;
            const size_t go = (size_t)(rowBase + r) * EE + k0 + c * 8;
            const uint32_t dst = b0 + (uint32_t)(r * 20 + c * 4) * 4;
            cp16(dst, agh + go, pred);
            cp16(dst + GKA * 4, agl + go, pred);
        }
        // B: 256 rows x 4 chunks each for hi and lo
        #pragma unroll
        for (int i = 0; i < 4; i++) {
            const int idx = tid + i * 256;
            const int n = idx >> 2;
            const int c = idx & 3;
            const size_t go = (size_t)(colBase + n) * EE + k0 + c * 8;
            const uint32_t dst = b0 + (uint32_t)(2 * GKA + n * 20 + c * 4) * 4;
            cp16(dst, bgh + go, true);
            cp16(dst + GKB * 4, bgl + go, true);
        }
        CP_COMMIT();
    };

    stage(0, 0);
    CP_WAIT0();
    __syncthreads();

    int buf = 0;
    for (int k0 = 0; k0 < EE; k0 += 32) {
        const bool more = (k0 + 32 < EE);
        if (more) stage(buf ^ 1, k0 + 32);   // DMA overlaps compute

        const uint32_t* ah = su + buf * GBUF;
        const uint32_t* al = ah + GKA;
        const uint32_t* bh = su + buf * GBUF + 2 * GKA;
        const uint32_t* bl = bh + GKB;

        #pragma unroll
        for (int ks = 0; ks < 2; ks++) {     // two k16 steps per k0=32
            // A fragments (hi+lo) for all 4 mf groups
            uint32_t aH[4][4], aL[4][4];
            #pragma unroll
            for (int mf = 0; mf < 4; mf++) {
                const int r0 = (wm + mf * 16 + g) * 20 + ks * 8 + tg;
                const int r1 = r0 + 8 * 20;
                aH[mf][0] = ah[r0];     aH[mf][1] = ah[r1];
                aH[mf][2] = ah[r0 + 4]; aH[mf][3] = ah[r1 + 4];
                aL[mf][0] = al[r0];     aL[mf][1] = al[r1];
                aL[mf][2] = al[r0 + 4]; aL[mf][3] = al[r1 + 4];
            }
            // B fragments (hi+lo)
            uint32_t bH[8][2], bL[8][2];
            #pragma unroll
            for (int nf = 0; nf < 8; nf++) {
                const int bb = (wn + nf * 8 + g) * 20 + ks * 8 + tg;
                bH[nf][0] = bh[bb]; bH[nf][1] = bh[bb + 4];
                bL[nf][0] = bl[bb]; bL[nf][1] = bl[bb + 4];
            }
            // 96 MMAs per ks: hi*hi + lo*hi + hi*lo
            #pragma unroll
            for (int mf = 0; mf < 4; mf++) {
                #pragma unroll
                for (int nf = 0; nf < 8; nf++) {
                    mma_bf16(acc[mf][nf], aH[mf][0], aH[mf][1], aH[mf][2], aH[mf][3],
                             bH[nf][0], bH[nf][1]);
                    mma_bf16(acc[mf][nf], aL[mf][0], aL[mf][1], aL[mf][2], aL[mf][3],
                             bH[nf][0], bH[nf][1]);
                    mma_bf16(acc[mf][nf], aH[mf][0], aH[mf][1], aH[mf][2], aH[mf][3],
                             bL[nf][0], bL[nf][1]);
                }
            }
        }
        if (more) CP_WAIT0();
        __syncthreads();
        buf ^= 1;
    }

    #pragma unroll
    for (int mf = 0; mf < 4; mf++) {
        const int row = rowBase + wm + mf * 16 + g;
        #pragma unroll
        for (int nf = 0; nf < 8; nf++) {
            const int col = colBase + wn + nf * 8 + 2 * tg;
            const float b0 = bias[col];
            const float b1 = bias[col + 1];
            if (row < M) {
                float2 o0 = make_float2(acc[mf][nf][0] + b0, acc[mf][nf][1] + b1);
                *(float2*)(C + (size_t)row * EE + col) = o0;
            }
            if (row + 8 < M) {
                float2 o1 = make_float2(acc[mf][nf][2] + b0, acc[mf][nf][3] + b1);
                *(float2*)(C + (size_t)(row + 8) * EE + col) = o1;
            }
        }
    }
}

// ---------------------------------------------------------------------------
// Tensor-core flash attention (2xTF32, R11 math unchanged).
// Epilogue writes bf16 hi/lo so the Wo GEMM needs no extra prep pass.
// Dynamic smem: 105472 B -> 2 CTAs/SM.
// ---------------------------------------------------------------------------
#define FQB 128
#define FKB 64
#define QS 68
#define KS 68
#define VS 72
#define PS 68
#define FSMEM_FLOATS (128*QS + 64*KS + 64*VS + 128*PS)   // 26368

__global__ __launch_bounds__(256, 2) void flash_attn_tc(
    const float* __restrict__ q, const float* __restrict__ k,
    const float* __restrict__ v,
    __nv_bfloat16* __restrict__ oh, __nv_bfloat16* __restrict__ ol)
{
    extern __shared__ float sm[];
    float* Qs = sm;
    float* Ks = Qs + 128 * QS;
    float* Vs = Ks + 64 * KS;
    float* Ps = Vs + 64 * VS;
    const uint32_t sQ = smem_u32(Qs);
    const uint32_t sK = smem_u32(Ks);
    const uint32_t sV = smem_u32(Vs);

    const int tid  = threadIdx.x;
    const int lane = tid & 31;
    const int wid  = tid >> 5;
    const int g    = lane >> 2;
    const int tg   = lane & 3;

    const int bh = blockIdx.x;
    const int b = bh >> 4;
    const int h = bh & 15;
    const int q0 = blockIdx.y * FQB;

    const size_t base = (size_t)b * TT * EE + (size_t)h * DD;
    const float* Q = q + base;
    const float* K = k + base;
    const float* V = v + base;

    #pragma unroll
    for (int i = 0; i < 8; i++) {
        const int idx = tid + i * 256;
        const int r = idx >> 4;
        const int c4 = (idx & 15) << 2;
        const int gr = q0 + r;
        cp16(sQ + (uint32_t)(r * QS + c4) * 4, Q + (size_t)gr * EE + c4, gr < TT);
    }
    CP_COMMIT();

    float m0 = -1e30f, m1 = -1e30f, l0 = 0.f, l1 = 0.f;
    float oacc[8][4];
    #pragma unroll
    for (int nf = 0; nf < 8; nf++)
        #pragma unroll
        for (int c = 0; c < 4; c++) oacc[nf][c] = 0.f;

    const int row0 = 16 * wid + g;
    const int row1 = row0 + 8;

    const int nkt = (TT + FKB - 1) / FKB;   // 10
    for (int kt = 0; kt < nkt; kt++) {
        const int kbase = kt * FKB;
        __syncthreads();

        #pragma unroll
        for (int i = 0; i < 4; i++) {
            const int idx = tid + i * 256;
            const int r = idx >> 4;
            const int c4 = (idx & 15) << 2;
            const int gr = kbase + r;
            cp16(sK + (uint32_t)(r * KS + c4) * 4, K + (size_t)gr * EE + c4, gr < TT);
            cp16(sV + (uint32_t)(r * VS + c4) * 4, V + (size_t)gr * EE + c4, gr < TT);
        }
        CP_COMMIT();
        CP_WAIT0();

        #pragma unroll
        for (int i = 0; i < 4; i++) {
            const int idx = tid + i * 256;
            const int r = idx >> 4;
            const int c4 = (idx & 15) << 2;
            float4* kp = (float4*)&Ks[r * KS + c4];
            float4 kv = *kp;
            kv.x = tf32f(kv.x); kv.y = tf32f(kv.y);
            kv.z = tf32f(kv.z); kv.w = tf32f(kv.w);
            *kp = kv;
            float4* vp = (float4*)&Vs[r * VS + c4];
            float4 vv = *vp;
            vv.x = tf32f(vv.x); vv.y = tf32f(vv.y);
            vv.z = tf32f(vv.z); vv.w = tf32f(vv.w);
            *vp = vv;
        }
        __syncthreads();

        float sacc[8][4];
        #pragma unroll
        for (int nf = 0; nf < 8; nf++)
            #pragma unroll
            for (int c = 0; c < 4; c++) sacc[nf][c] = 0.f;

        #pragma unroll
        for (int kd = 0; kd < 8; kd++) {
            const int ar0 = row0 * QS + kd * 8 + tg;
            const int ar1 = ar0 + 8 * QS;
            uint32_t aH0, aH1, aH2, aH3, aL0, aL1, aL2, aL3;
            split_u(Qs[ar0],     aH0, aL0);
            split_u(Qs[ar1],     aH1, aL1);
            split_u(Qs[ar0 + 4], aH2, aL2);
            split_u(Qs[ar1 + 4], aH3, aL3);
            #pragma unroll
            for (int nf = 0; nf < 8; nf++) {
                const int br = (8 * nf + g) * KS + kd * 8 + tg;
                const uint32_t bH0 = __float_as_uint(Ks[br]);
                const uint32_t bH1 = __float_as_uint(Ks[br + 4]);
                mma_tf32(sacc[nf], aH0, aH1, aH2, aH3, bH0, bH1);
                mma_tf32(sacc[nf], aL0, aL1, aL2, aL3, bH0, bH1);
            }
        }

        float mx0 = -1e30f, mx1 = -1e30f;
        #pragma unroll
        for (int nf = 0; nf < 8; nf++) {
            const int kc0 = kbase + 8 * nf + 2 * tg;
            const int kc1 = kc0 + 1;
            sacc[nf][0] = (kc0 < TT) ? sacc[nf][0] * 0.125f : -1e30f;
            sacc[nf][1] = (kc1 < TT) ? sacc[nf][1] * 0.125f : -1e30f;
            sacc[nf][2] = (kc0 < TT) ? sacc[nf][2] * 0.125f : -1e30f;
            sacc[nf][3] = (kc1 < TT) ? sacc[nf][3] * 0.125f : -1e30f;
            mx0 = fmaxf(mx0, fmaxf(sacc[nf][0], sacc[nf][1]));
            mx1 = fmaxf(mx1, fmaxf(sacc[nf][2], sacc[nf][3]));
        }
        mx0 = fmaxf(mx0, __shfl_xor_sync(0xffffffffu, mx0, 1));
        mx0 = fmaxf(mx0, __shfl_xor_sync(0xffffffffu, mx0, 2));
        mx1 = fmaxf(mx1, __shfl_xor_sync(0xffffffffu, mx1, 1));
        mx1 = fmaxf(mx1, __shfl_xor_sync(0xffffffffu, mx1, 2));

        const float mn0 = fmaxf(m0, mx0);
        const float mn1 = fmaxf(m1, mx1);
        const float cc0 = __expf(m0 - mn0);
        const float cc1 = __expf(m1 - mn1);
        m0 = mn0; m1 = mn1;

        float rs0 = 0.f, rs1 = 0.f;
        #pragma unroll
        for (int nf = 0; nf < 8; nf++) {
            const float p0 = __expf(sacc[nf][0] - m0);
            const float p1 = __expf(sacc[nf][1] - m0);
            const float p2 = __expf(sacc[nf][2] - m1);
            const float p3 = __expf(sacc[nf][3] - m1);
            rs0 += p0 + p1;
            rs1 += p2 + p3;
            const int col = 8 * nf + 2 * tg;
            *(float2*)&Ps[row0 * PS + col] = make_float2(p0, p1);
            *(float2*)&Ps[row1 * PS + col] = make_float2(p2, p3);
        }
        rs0 += __shfl_xor_sync(0xffffffffu, rs0, 1);
        rs0 += __shfl_xor_sync(0xffffffffu, rs0, 2);
        rs1 += __shfl_xor_sync(0xffffffffu, rs1, 1);
        rs1 += __shfl_xor_sync(0xffffffffu, rs1, 2);
        l0 = l0 * cc0 + rs0;
        l1 = l1 * cc1 + rs1;

        #pragma unroll
        for (int nf = 0; nf < 8; nf++) {
            oacc[nf][0] *= cc0;
            oacc[nf][1] *= cc0;
            oacc[nf][2] *= cc1;
            oacc[nf][3] *= cc1;
        }
        __syncwarp();

        #pragma unroll
        for (int kc = 0; kc < 8; kc++) {
            const int ar0 = row0 * PS + kc * 8 + tg;
            const int ar1 = ar0 + 8 * PS;
            uint32_t aH0, aH1, aH2, aH3, aL0, aL1, aL2, aL3;
            split_u(Ps[ar0],     aH0, aL0);
            split_u(Ps[ar1],     aH1, aL1);
            split_u(Ps[ar0 + 4], aH2, aL2);
            split_u(Ps[ar1 + 4], aH3, aL3);
            #pragma unroll
            for (int nfd = 0; nfd < 8; nfd++) {
                const int br0 = (kc * 8 + tg) * VS + nfd * 8 + g;
                const int br1 = br0 + 4 * VS;
                const uint32_t bH0 = __float_as_uint(Vs[br0]);
                const uint32_t bH1 = __float_as_uint(Vs[br1]);
                mma_tf32(oacc[nfd], aH0, aH1, aH2, aH3, bH0, bH1);
                mma_tf32(oacc[nfd], aL0, aL1, aL2, aL3, bH0, bH1);
            }
        }
    }

    // epilogue: normalize + store bf16 hi/lo for the Wo GEMM
    const float inv0 = 1.f / l0;
    const float inv1 = 1.f / l1;
    const int gr0 = q0 + row0;
    const int gr1 = q0 + row1;
    #pragma unroll
    for (int nfd = 0; nfd < 8; nfd++) {
        const int col = nfd * 8 + 2 * tg;
        if (gr0 < TT) {
            const float o0 = oacc[nfd][0] * inv0;
            const float o1 = oacc[nfd][1] * inv0;
            const uint32_t hp = pack_bf16(o0, o1);
            const uint32_t lp = pack_bf16(o0 - bf16lo_f(hp), o1 - bf16hi_f(hp));
            const size_t off = base + (size_t)gr0 * EE + col;
            *(uint32_t*)(oh + off) = hp;
            *(uint32_t*)(ol + off) = lp;
        }
        if (gr1 < TT) {
            const float o0 = oacc[nfd][2] * inv1;
            const float o1 = oacc[nfd][3] * inv1;
            const uint32_t hp = pack_bf16(o0, o1);
            const uint32_t lp = pack_bf16(o0 - bf16lo_f(hp), o1 - bf16hi_f(hp));
            const size_t off = base + (size_t)gr1 * EE + col;
            *(uint32_t*)(oh + off) = hp;
            *(uint32_t*)(ol + off) = lp;
        }
    }
}

// ---------------------------------------------------------------------------
// Launch
// ---------------------------------------------------------------------------
extern "C" void kernel_launch(void* const* d_in, const int* in_sizes, int n_in,
                              void* d_out, int out_size)
{
    const float* x  = (const float*)d_in[0];
    const float* Wq = (const float*)d_in[1];
    const float* bq = (const float*)d_in[2];
    const float* Wk = (const float*)d_in[3];
    const float* bk = (const float*)d_in[4];
    const float* Wv = (const float*)d_in[5];
    const float* bv = (const float*)d_in[6];
    const float* Wo = (const float*)d_in[7];
    const float* bo = (const float*)d_in[8];
    float* out = (float*)d_out;

    float *gq, *gk, *gv;
    __nv_bfloat16 *xh, *xl, *ah, *al, *wth, *wtl;
    cudaGetSymbolAddress((void**)&gq, g_q);
    cudaGetSymbolAddress((void**)&gk, g_k);
    cudaGetSymbolAddress((void**)&gv, g_v);
    cudaGetSymbolAddress((void**)&xh, g_xh);
    cudaGetSymbolAddress((void**)&xl, g_xl);
    cudaGetSymbolAddress((void**)&ah, g_ah);
    cudaGetSymbolAddress((void**)&al, g_al);
    cudaGetSymbolAddress((void**)&wth, g_wth);
    cudaGetSymbolAddress((void**)&wtl, g_wtl);

    const int smemG = GSMEM_B;            // 122880
    const int smemF = FSMEM_FLOATS * 4;   // 105472
    cudaFuncSetAttribute(gemm_bf16x3, cudaFuncAttributeMaxDynamicSharedMemorySize, smemG);
    cudaFuncSetAttribute(flash_attn_tc, cudaFuncAttributeMaxDynamicSharedMemorySize, smemF);

    // prep: split x, transpose+split the 4 weight matrices
    const int n4 = MM * EE / 4;
    prep_x<<<(n4 + 255) / 256, 256>>>(x, xh, xl, n4);
    dim3 gridW(EE / 64, EE / 64);         // (16,16)
    const size_t wsz = (size_t)EE * EE;
    prep_w<<<gridW, 256>>>(Wq, wth + 0 * wsz, wtl + 0 * wsz);
    prep_w<<<gridW, 256>>>(Wk, wth + 1 * wsz, wtl + 1 * wsz);
    prep_w<<<gridW, 256>>>(Wv, wth + 2 * wsz, wtl + 2 * wsz);
    prep_w<<<gridW, 256>>>(Wo, wth + 3 * wsz, wtl + 3 * wsz);

    // projections (bf16x3 mma.sync)
    dim3 gridG(EE / GBN, (MM + 127) / 128);   // (4, 145)
    gemm_bf16x3<<<gridG, 256, smemG>>>(xh, xl, wth + 0 * wsz, wtl + 0 * wsz, bq, gq, MM);
    gemm_bf16x3<<<gridG, 256, smemG>>>(xh, xl, wth + 1 * wsz, wtl + 1 * wsz, bk, gk, MM);
    gemm_bf16x3<<<gridG, 256, smemG>>>(xh, xl, wth + 2 * wsz, wtl + 2 * wsz, bv, gv, MM);

    // attention
    dim3 gridA(BB * HH, (TT + FQB - 1) / FQB);  // (512, 5)
    flash_attn_tc<<<gridA, 256, smemF>>>(gq, gk, gv, ah, al);

    // output projection
    gemm_bf16x3<<<gridG, 256, smemG>>>(ah, al, wth + 3 * wsz, wtl + 3 * wsz, bo, out, MM);
}

// round 15
// speedup vs baseline: 1.2194x; 1.0022x over previous
#include <cuda_runtime.h>
#include <cuda_bf16.h>
#include <math.h>
#include <stdint.h>

// Problem constants
#define BB 32
#define TT 577
#define EE 1024
#define HH 16
#define DD 64
#define MM (BB * TT)   // 18464 rows

// Scratch (alloc-free rule: __device__ globals)
__device__ float g_q[(size_t)MM * EE];
__device__ float g_k[(size_t)MM * EE];
__device__ float g_v[(size_t)MM * EE];
__device__ __nv_bfloat16 g_xh[(size_t)MM * EE];
__device__ __nv_bfloat16 g_xl[(size_t)MM * EE];
__device__ __nv_bfloat16 g_ah[(size_t)MM * EE];
__device__ __nv_bfloat16 g_al[(size_t)MM * EE];
__device__ __nv_bfloat16 g_wth[(size_t)4 * EE * EE];   // W^T hi, [n][k]
__device__ __nv_bfloat16 g_wtl[(size_t)4 * EE * EE];   // W^T lo

// ---------------------------------------------------------------------------
// common helpers
// ---------------------------------------------------------------------------
__device__ __forceinline__ uint32_t smem_u32(const void* p) {
    return (uint32_t)__cvta_generic_to_shared(p);
}
__device__ __forceinline__ void cp16(uint32_t dst, const void* src, bool pred) {
    asm volatile("cp.async.cg.shared.global [%0], [%1], 16, %2;\n"
                 :: "r"(dst), "l"(src), "r"(pred ? 16 : 0));
}
#define CP_COMMIT() asm volatile("cp.async.commit_group;\n" ::: "memory")
#define CP_WAIT0()  asm volatile("cp.async.wait_group 0;\n" ::: "memory")

// pack_bf16(a, b) -> u32 with mem order [bf16(a), bf16(b)]
__device__ __forceinline__ uint32_t pack_bf16(float lo, float hi) {
    uint32_t r;
    asm("cvt.rn.bf16x2.f32 %0, %1, %2;" : "=r"(r) : "f"(hi), "f"(lo));
    return r;
}
__device__ __forceinline__ float bf16lo_f(uint32_t p) { return __uint_as_float(p << 16); }
__device__ __forceinline__ float bf16hi_f(uint32_t p) { return __uint_as_float(p & 0xffff0000u); }

// tf32 helpers (flash attention, unchanged math)
__device__ __forceinline__ void split_u(float x, uint32_t& hi, uint32_t& lo) {
    uint32_t uh;
    asm("cvt.rna.tf32.f32 %0, %1;" : "=r"(uh) : "f"(x));
    hi = uh;
    lo = __float_as_uint(x - __uint_as_float(uh));
}
__device__ __forceinline__ float tf32f(float x) {
    uint32_t u;
    asm("cvt.rna.tf32.f32 %0, %1;" : "=r"(u) : "f"(x));
    return __uint_as_float(u);
}
__device__ __forceinline__ void mma_tf32(float* acc,
                                         uint32_t a0, uint32_t a1, uint32_t a2, uint32_t a3,
                                         uint32_t b0, uint32_t b1) {
    asm volatile(
        "mma.sync.aligned.m16n8k8.row.col.f32.tf32.tf32.f32 "
        "{%0,%1,%2,%3}, {%4,%5,%6,%7}, {%8,%9}, {%0,%1,%2,%3};\n"
        : "+f"(acc[0]), "+f"(acc[1]), "+f"(acc[2]), "+f"(acc[3])
        : "r"(a0), "r"(a1), "r"(a2), "r"(a3), "r"(b0), "r"(b1));
}

// bf16 m16n8k16 MMA (A row-major, B col-major i.e. [N][K])
__device__ __forceinline__ void mma_bf16(float* acc,
                                         uint32_t a0, uint32_t a1, uint32_t a2, uint32_t a3,
                                         uint32_t b0, uint32_t b1) {
    asm volatile(
        "mma.sync.aligned.m16n8k16.row.col.f32.bf16.bf16.f32 "
        "{%0,%1,%2,%3}, {%4,%5,%6,%7}, {%8,%9}, {%0,%1,%2,%3};\n"
        : "+f"(acc[0]), "+f"(acc[1]), "+f"(acc[2]), "+f"(acc[3])
        : "r"(a0), "r"(a1), "r"(a2), "r"(a3), "r"(b0), "r"(b1));
}

// ---------------------------------------------------------------------------
// prep kernels: fp32 -> bf16 hi/lo splits
// ---------------------------------------------------------------------------
__global__ void prep_x(const float* __restrict__ x,
                       __nv_bfloat16* __restrict__ xh,
                       __nv_bfloat16* __restrict__ xl, int n4) {
    int idx = blockIdx.x * 256 + threadIdx.x;
    if (idx >= n4) return;
    float4 v = ((const float4*)x)[idx];
    uint32_t h0 = pack_bf16(v.x, v.y);
    uint32_t h1 = pack_bf16(v.z, v.w);
    uint32_t l0 = pack_bf16(v.x - bf16lo_f(h0), v.y - bf16hi_f(h0));
    uint32_t l1 = pack_bf16(v.z - bf16lo_f(h1), v.w - bf16hi_f(h1));
    ((uint2*)xh)[idx] = make_uint2(h0, h1);
    ((uint2*)xl)[idx] = make_uint2(l0, l1);
}

// transpose + split: W[k][n] fp32 -> Wt_h/Wt_l [n][k] bf16 (64x64 tiles)
// NOTE: stride 68 (272 B = 17*16) keeps the float4 staging stores 16B-aligned
// (stride 65 was the R13 misaligned-address bug).
__global__ __launch_bounds__(256) void prep_w(const float* __restrict__ W,
                                              __nv_bfloat16* __restrict__ wth,
                                              __nv_bfloat16* __restrict__ wtl) {
    __shared__ float s[64][68];
    const int tid = threadIdx.x;
    const int k0 = blockIdx.y * 64, n0 = blockIdx.x * 64;
    #pragma unroll
    for (int i = 0; i < 4; i++) {
        const int idx = tid + i * 256;
        const int kk = idx >> 4;
        const int n4 = (idx & 15) * 4;
        *(float4*)&s[kk][n4] = *(const float4*)(W + (size_t)(k0 + kk) * EE + n0 + n4);
    }
    __syncthreads();
    #pragma unroll
    for (int i = 0; i < 4; i++) {
        const int idx = tid + i * 256;
        const int nn = idx >> 4;
        const int k4 = (idx & 15) * 4;
        float s0 = s[k4 + 0][nn], s1 = s[k4 + 1][nn];
        float s2 = s[k4 + 2][nn], s3 = s[k4 + 3][nn];
        uint32_t h0 = pack_bf16(s0, s1), h1 = pack_bf16(s2, s3);
        uint32_t l0 = pack_bf16(s0 - bf16lo_f(h0), s1 - bf16hi_f(h0));
        uint32_t l1 = pack_bf16(s2 - bf16lo_f(h1), s3 - bf16hi_f(h1));
        const size_t off = (size_t)(n0 + nn) * EE + k0 + k4;
        *(uint2*)(wth + off) = make_uint2(h0, h1);
        *(uint2*)(wtl + off) = make_uint2(l0, l1);
    }
}

// ---------------------------------------------------------------------------
// GEMM (3xBF16, mma.sync m16n8k16): C[M,1024] = A @ W + bias
// A: bf16 hi/lo [M][K]; B: bf16 hi/lo [N][K] (pre-transposed W).
// Block tile 128x256, BK=32 elems, 8 warps (2x4), warp tile 64x64.
// smem: packed bf16 (u32), row stride 20 u32 (banks 20g+tg all distinct).
// Per k0=32: 192 MMA + 128 LDS.32, zero cvt. Double-buffered cp.async.
// smem total: 2 * (2*2560 + 2*5120) u32 = 122880 B. 1 CTA/SM.
// ---------------------------------------------------------------------------
#define GBN 256
#define GKA 2560     // u32 per A hi/lo buffer (128 rows x 20)
#define GKB 5120     // u32 per B hi/lo buffer (256 rows x 20)
#define GBUF (2 * GKA + 2 * GKB)   // 15360 u32 per stage
#define GSMEM_B (2 * GBUF * 4)     // 122880 bytes

__global__ __launch_bounds__(256, 1) void gemm_bf16x3(
    const __nv_bfloat16* __restrict__ agh, const __nv_bfloat16* __restrict__ agl,
    const __nv_bfloat16* __restrict__ bgh, const __nv_bfloat16* __restrict__ bgl,
    const float* __restrict__ bias, float* __restrict__ C, int M)
{
    extern __shared__ uint32_t su[];
    const uint32_t sbase = smem_u32(su);

    const int tid  = threadIdx.x;
    const int lane = tid & 31;
    const int wid  = tid >> 5;        // 0..7
    const int g    = lane >> 2;       // 0..7
    const int tg   = lane & 3;        // 0..3
    const int wm   = (wid >> 2) * 64; // warp row offset (0/64)
    const int wn   = (wid & 3) * 64;  // warp col offset (0/64/128/192)
    const int rowBase = blockIdx.y * 128;
    const int colBase = blockIdx.x * GBN;

    float acc[4][8][4];
    #pragma unroll
    for (int mf = 0; mf < 4; mf++)
        #pragma unroll
        for (int nf = 0; nf < 8; nf++)
            #pragma unroll
            for (int c = 0; c < 4; c++) acc[mf][nf][c] = 0.f;

    auto stage = [&](int buf, int k0) {   // k0 in bf16 elements
        const uint32_t b0 = sbase + (uint32_t)buf * GBUF * 4;
        // A: 128 rows x 4 chunks (16B = 8 bf16) each for hi and lo
        #pragma unroll
        for (int i = 0; i < 2; i++) {
            const int idx = tid + i * 256;
            const int r = idx >> 2;
            const int c = idx & 3;
            const bool pred = (rowBase + r) < M;
            const size_t go = (size_t)(rowBase + r) * EE + k0 + c * 8;
            const uint32_t dst = b0 + (uint32_t)(r * 20 + c * 4) * 4;
            cp16(dst, agh + go, pred);
            cp16(dst + GKA * 4, agl + go, pred);
        }
        // B: 256 rows x 4 chunks each for hi and lo
        #pragma unroll
        for (int i = 0; i < 4; i++) {
            const int idx = tid + i * 256;
            const int n = idx >> 2;
            const int c = idx & 3;
            const size_t go = (size_t)(colBase + n) * EE + k0 + c * 8;
            const uint32_t dst = b0 + (uint32_t)(2 * GKA + n * 20 + c * 4) * 4;
            cp16(dst, bgh + go, true);
            cp16(dst + GKB * 4, bgl + go, true);
        }
        CP_COMMIT();
    };

    stage(0, 0);
    CP_WAIT0();
    __syncthreads();

    int buf = 0;
    for (int k0 = 0; k0 < EE; k0 += 32) {
        const bool more = (k0 + 32 < EE);
        if (more) stage(buf ^ 1, k0 + 32);   // DMA overlaps compute

        const uint32_t* ah = su + buf * GBUF;
        const uint32_t* al = ah + GKA;
        const uint32_t* bh = su + buf * GBUF + 2 * GKA;
        const uint32_t* bl = bh + GKB;

        #pragma unroll
        for (int ks = 0; ks < 2; ks++) {     // two k16 steps per k0=32
            // A fragments (hi+lo) for all 4 mf groups
            uint32_t aH[4][4], aL[4][4];
            #pragma unroll
            for (int mf = 0; mf < 4; mf++) {
                const int r0 = (wm + mf * 16 + g) * 20 + ks * 8 + tg;
                const int r1 = r0 + 8 * 20;
                aH[mf][0] = ah[r0];     aH[mf][1] = ah[r1];
                aH[mf][2] = ah[r0 + 4]; aH[mf][3] = ah[r1 + 4];
                aL[mf][0] = al[r0];     aL[mf][1] = al[r1];
                aL[mf][2] = al[r0 + 4]; aL[mf][3] = al[r1 + 4];
            }
            // B fragments (hi+lo)
            uint32_t bH[8][2], bL[8][2];
            #pragma unroll
            for (int nf = 0; nf < 8; nf++) {
                const int bb = (wn + nf * 8 + g) * 20 + ks * 8 + tg;
                bH[nf][0] = bh[bb]; bH[nf][1] = bh[bb + 4];
                bL[nf][0] = bl[bb]; bL[nf][1] = bl[bb + 4];
            }
            // 96 MMAs per ks: hi*hi + lo*hi + hi*lo
            #pragma unroll
            for (int mf = 0; mf < 4; mf++) {
                #pragma unroll
                for (int nf = 0; nf < 8; nf++) {
                    mma_bf16(acc[mf][nf], aH[mf][0], aH[mf][1], aH[mf][2], aH[mf][3],
                             bH[nf][0], bH[nf][1]);
                    mma_bf16(acc[mf][nf], aL[mf][0], aL[mf][1], aL[mf][2], aL[mf][3],
                             bH[nf][0], bH[nf][1]);
                    mma_bf16(acc[mf][nf], aH[mf][0], aH[mf][1], aH[mf][2], aH[mf][3],
                             bL[nf][0], bL[nf][1]);
                }
            }
        }
        if (more) CP_WAIT0();
        __syncthreads();
        buf ^= 1;
    }

    #pragma unroll
    for (int mf = 0; mf < 4; mf++) {
        const int row = rowBase + wm + mf * 16 + g;
        #pragma unroll
        for (int nf = 0; nf < 8; nf++) {
            const int col = colBase + wn + nf * 8 + 2 * tg;
            const float b0 = bias[col];
            const float b1 = bias[col + 1];
            if (row < M) {
                float2 o0 = make_float2(acc[mf][nf][0] + b0, acc[mf][nf][1] + b1);
                *(float2*)(C + (size_t)row * EE + col) = o0;
            }
            if (row + 8 < M) {
                float2 o1 = make_float2(acc[mf][nf][2] + b0, acc[mf][nf][3] + b1);
                *(float2*)(C + (size_t)(row + 8) * EE + col) = o1;
            }
        }
    }
}

// ---------------------------------------------------------------------------
// Tensor-core flash attention (2xTF32, R11 math unchanged).
// Epilogue writes bf16 hi/lo so the Wo GEMM needs no extra prep pass.
// Dynamic smem: 105472 B -> 2 CTAs/SM.
// ---------------------------------------------------------------------------
#define FQB 128
#define FKB 64
#define QS 68
#define KS 68
#define VS 72
#define PS 68
#define FSMEM_FLOATS (128*QS + 64*KS + 64*VS + 128*PS)   // 26368

__global__ __launch_bounds__(256, 2) void flash_attn_tc(
    const float* __restrict__ q, const float* __restrict__ k,
    const float* __restrict__ v,
    __nv_bfloat16* __restrict__ oh, __nv_bfloat16* __restrict__ ol)
{
    extern __shared__ float sm[];
    float* Qs = sm;
    float* Ks = Qs + 128 * QS;
    float* Vs = Ks + 64 * KS;
    float* Ps = Vs + 64 * VS;
    const uint32_t sQ = smem_u32(Qs);
    const uint32_t sK = smem_u32(Ks);
    const uint32_t sV = smem_u32(Vs);

    const int tid  = threadIdx.x;
    const int lane = tid & 31;
    const int wid  = tid >> 5;
    const int g    = lane >> 2;
    const int tg   = lane & 3;

    const int bh = blockIdx.x;
    const int b = bh >> 4;
    const int h = bh & 15;
    const int q0 = blockIdx.y * FQB;

    const size_t base = (size_t)b * TT * EE + (size_t)h * DD;
    const float* Q = q + base;
    const float* K = k + base;
    const float* V = v + base;

    #pragma unroll
    for (int i = 0; i < 8; i++) {
        const int idx = tid + i * 256;
        const int r = idx >> 4;
        const int c4 = (idx & 15) << 2;
        const int gr = q0 + r;
        cp16(sQ + (uint32_t)(r * QS + c4) * 4, Q + (size_t)gr * EE + c4, gr < TT);
    }
    CP_COMMIT();

    float m0 = -1e30f, m1 = -1e30f, l0 = 0.f, l1 = 0.f;
    float oacc[8][4];
    #pragma unroll
    for (int nf = 0; nf < 8; nf++)
        #pragma unroll
        for (int c = 0; c < 4; c++) oacc[nf][c] = 0.f;

    const int row0 = 16 * wid + g;
    const int row1 = row0 + 8;

    const int nkt = (TT + FKB - 1) / FKB;   // 10
    for (int kt = 0; kt < nkt; kt++) {
        const int kbase = kt * FKB;
        __syncthreads();

        #pragma unroll
        for (int i = 0; i < 4; i++) {
            const int idx = tid + i * 256;
            const int r = idx >> 4;
            const int c4 = (idx & 15) << 2;
            const int gr = kbase + r;
            cp16(sK + (uint32_t)(r * KS + c4) * 4, K + (size_t)gr * EE + c4, gr < TT);
            cp16(sV + (uint32_t)(r * VS + c4) * 4, V + (size_t)gr * EE + c4, gr < TT);
        }
        CP_COMMIT();
        CP_WAIT0();

        #pragma unroll
        for (int i = 0; i < 4; i++) {
            const int idx = tid + i * 256;
            const int r = idx >> 4;
            const int c4 = (idx & 15) << 2;
            float4* kp = (float4*)&Ks[r * KS + c4];
            float4 kv = *kp;
            kv.x = tf32f(kv.x); kv.y = tf32f(kv.y);
            kv.z = tf32f(kv.z); kv.w = tf32f(kv.w);
            *kp = kv;
            float4* vp = (float4*)&Vs[r * VS + c4];
            float4 vv = *vp;
            vv.x = tf32f(vv.x); vv.y = tf32f(vv.y);
            vv.z = tf32f(vv.z); vv.w = tf32f(vv.w);
            *vp = vv;
        }
        __syncthreads();

        float sacc[8][4];
        #pragma unroll
        for (int nf = 0; nf < 8; nf++)
            #pragma unroll
            for (int c = 0; c < 4; c++) sacc[nf][c] = 0.f;

        #pragma unroll
        for (int kd = 0; kd < 8; kd++) {
            const int ar0 = row0 * QS + kd * 8 + tg;
            const int ar1 = ar0 + 8 * QS;
            uint32_t aH0, aH1, aH2, aH3, aL0, aL1, aL2, aL3;
            split_u(Qs[ar0],     aH0, aL0);
            split_u(Qs[ar1],     aH1, aL1);
            split_u(Qs[ar0 + 4], aH2, aL2);
            split_u(Qs[ar1 + 4], aH3, aL3);
            #pragma unroll
            for (int nf = 0; nf < 8; nf++) {
                const int br = (8 * nf + g) * KS + kd * 8 + tg;
                const uint32_t bH0 = __float_as_uint(Ks[br]);
                const uint32_t bH1 = __float_as_uint(Ks[br + 4]);
                mma_tf32(sacc[nf], aH0, aH1, aH2, aH3, bH0, bH1);
                mma_tf32(sacc[nf], aL0, aL1, aL2, aL3, bH0, bH1);
            }
        }

        float mx0 = -1e30f, mx1 = -1e30f;
        #pragma unroll
        for (int nf = 0; nf < 8; nf++) {
            const int kc0 = kbase + 8 * nf + 2 * tg;
            const int kc1 = kc0 + 1;
            sacc[nf][0] = (kc0 < TT) ? sacc[nf][0] * 0.125f : -1e30f;
            sacc[nf][1] = (kc1 < TT) ? sacc[nf][1] * 0.125f : -1e30f;
            sacc[nf][2] = (kc0 < TT) ? sacc[nf][2] * 0.125f : -1e30f;
            sacc[nf][3] = (kc1 < TT) ? sacc[nf][3] * 0.125f : -1e30f;
            mx0 = fmaxf(mx0, fmaxf(sacc[nf][0], sacc[nf][1]));
            mx1 = fmaxf(mx1, fmaxf(sacc[nf][2], sacc[nf][3]));
        }
        mx0 = fmaxf(mx0, __shfl_xor_sync(0xffffffffu, mx0, 1));
        mx0 = fmaxf(mx0, __shfl_xor_sync(0xffffffffu, mx0, 2));
        mx1 = fmaxf(mx1, __shfl_xor_sync(0xffffffffu, mx1, 1));
        mx1 = fmaxf(mx1, __shfl_xor_sync(0xffffffffu, mx1, 2));

        const float mn0 = fmaxf(m0, mx0);
        const float mn1 = fmaxf(m1, mx1);
        const float cc0 = __expf(m0 - mn0);
        const float cc1 = __expf(m1 - mn1);
        m0 = mn0; m1 = mn1;

        float rs0 = 0.f, rs1 = 0.f;
        #pragma unroll
        for (int nf = 0; nf < 8; nf++) {
            const float p0 = __expf(sacc[nf][0] - m0);
            const float p1 = __expf(sacc[nf][1] - m0);
            const float p2 = __expf(sacc[nf][2] - m1);
            const float p3 = __expf(sacc[nf][3] - m1);
            rs0 += p0 + p1;
            rs1 += p2 + p3;
            const int col = 8 * nf + 2 * tg;
            *(float2*)&Ps[row0 * PS + col] = make_float2(p0, p1);
            *(float2*)&Ps[row1 * PS + col] = make_float2(p2, p3);
        }
        rs0 += __shfl_xor_sync(0xffffffffu, rs0, 1);
        rs0 += __shfl_xor_sync(0xffffffffu, rs0, 2);
        rs1 += __shfl_xor_sync(0xffffffffu, rs1, 1);
        rs1 += __shfl_xor_sync(0xffffffffu, rs1, 2);
        l0 = l0 * cc0 + rs0;
        l1 = l1 * cc1 + rs1;

        #pragma unroll
        for (int nf = 0; nf < 8; nf++) {
            oacc[nf][0] *= cc0;
            oacc[nf][1] *= cc0;
            oacc[nf][2] *= cc1;
            oacc[nf][3] *= cc1;
        }
        __syncwarp();

        #pragma unroll
        for (int kc = 0; kc < 8; kc++) {
            const int ar0 = row0 * PS + kc * 8 + tg;
            const int ar1 = ar0 + 8 * PS;
            uint32_t aH0, aH1, aH2, aH3, aL0, aL1, aL2, aL3;
            split_u(Ps[ar0],     aH0, aL0);
            split_u(Ps[ar1],     aH1, aL1);
            split_u(Ps[ar0 + 4], aH2, aL2);
            split_u(Ps[ar1 + 4], aH3, aL3);
            #pragma unroll
            for (int nfd = 0; nfd < 8; nfd++) {
                const int br0 = (kc * 8 + tg) * VS + nfd * 8 + g;
                const int br1 = br0 + 4 * VS;
                const uint32_t bH0 = __float_as_uint(Vs[br0]);
                const uint32_t bH1 = __float_as_uint(Vs[br1]);
                mma_tf32(oacc[nfd], aH0, aH1, aH2, aH3, bH0, bH1);
                mma_tf32(oacc[nfd], aL0, aL1, aL2, aL3, bH0, bH1);
            }
        }
    }

    // epilogue: normalize + store bf16 hi/lo for the Wo GEMM
    const float inv0 = 1.f / l0;
    const float inv1 = 1.f / l1;
    const int gr0 = q0 + row0;
    const int gr1 = q0 + row1;
    #pragma unroll
    for (int nfd = 0; nfd < 8; nfd++) {
        const int col = nfd * 8 + 2 * tg;
        if (gr0 < TT) {
            const float o0 = oacc[nfd][0] * inv0;
            const float o1 = oacc[nfd][1] * inv0;
            const uint32_t hp = pack_bf16(o0, o1);
            const uint32_t lp = pack_bf16(o0 - bf16lo_f(hp), o1 - bf16hi_f(hp));
            const size_t off = base + (size_t)gr0 * EE + col;
            *(uint32_t*)(oh + off) = hp;
            *(uint32_t*)(ol + off) = lp;
        }
        if (gr1 < TT) {
            const float o0 = oacc[nfd][2] * inv1;
            const float o1 = oacc[nfd][3] * inv1;
            const uint32_t hp = pack_bf16(o0, o1);
            const uint32_t lp = pack_bf16(o0 - bf16lo_f(hp), o1 - bf16hi_f(hp));
            const size_t off = base + (size_t)gr1 * EE + col;
            *(uint32_t*)(oh + off) = hp;
            *(uint32_t*)(ol + off) = lp;
        }
    }
}

// ---------------------------------------------------------------------------
// Launch
// ---------------------------------------------------------------------------
extern "C" void kernel_launch(void* const* d_in, const int* in_sizes, int n_in,
                              void* d_out, int out_size)
{
    const float* x  = (const float*)d_in[0];
    const float* Wq = (const float*)d_in[1];
    const float* bq = (const float*)d_in[2];
    const float* Wk = (const float*)d_in[3];
    const float* bk = (const float*)d_in[4];
    const float* Wv = (const float*)d_in[5];
    const float* bv = (const float*)d_in[6];
    const float* Wo = (const float*)d_in[7];
    const float* bo = (const float*)d_in[8];
    float* out = (float*)d_out;

    float *gq, *gk, *gv;
    __nv_bfloat16 *xh, *xl, *ah, *al, *wth, *wtl;
    cudaGetSymbolAddress((void**)&gq, g_q);
    cudaGetSymbolAddress((void**)&gk, g_k);
    cudaGetSymbolAddress((void**)&gv, g_v);
    cudaGetSymbolAddress((void**)&xh, g_xh);
    cudaGetSymbolAddress((void**)&xl, g_xl);
    cudaGetSymbolAddress((void**)&ah, g_ah);
    cudaGetSymbolAddress((void**)&al, g_al);
    cudaGetSymbolAddress((void**)&wth, g_wth);
    cudaGetSymbolAddress((void**)&wtl, g_wtl);

    const int smemG = GSMEM_B;            // 122880
    const int smemF = FSMEM_FLOATS * 4;   // 105472
    cudaFuncSetAttribute(gemm_bf16x3, cudaFuncAttributeMaxDynamicSharedMemorySize, smemG);
    cudaFuncSetAttribute(flash_attn_tc, cudaFuncAttributeMaxDynamicSharedMemorySize, smemF);

    // prep: split x, transpose+split the 4 weight matrices
    const int n4 = MM * EE / 4;
    prep_x<<<(n4 + 255) / 256, 256>>>(x, xh, xl, n4);
    dim3 gridW(EE / 64, EE / 64);         // (16,16)
    const size_t wsz = (size_t)EE * EE;
    prep_w<<<gridW, 256>>>(Wq, wth + 0 * wsz, wtl + 0 * wsz);
    prep_w<<<gridW, 256>>>(Wk, wth + 1 * wsz, wtl + 1 * wsz);
    prep_w<<<gridW, 256>>>(Wv, wth + 2 * wsz, wtl + 2 * wsz);
    prep_w<<<gridW, 256>>>(Wo, wth + 3 * wsz, wtl + 3 * wsz);

    // projections (bf16x3 mma.sync)
    dim3 gridG(EE / GBN, (MM + 127) / 128);   // (4, 145)
    gemm_bf16x3<<<gridG, 256, smemG>>>(xh, xl, wth + 0 * wsz, wtl + 0 * wsz, bq, gq, MM);
    gemm_bf16x3<<<gridG, 256, smemG>>>(xh, xl, wth + 1 * wsz, wtl + 1 * wsz, bk, gk, MM);
    gemm_bf16x3<<<gridG, 256, smemG>>>(xh, xl, wth + 2 * wsz, wtl + 2 * wsz, bv, gv, MM);

    // attention
    dim3 gridA(BB * HH, (TT + FQB - 1) / FQB);  // (512, 5)
    flash_attn_tc<<<gridA, 256, smemF>>>(gq, gk, gv, ah, al);

    // output projection
    gemm_bf16x3<<<gridG, 256, smemG>>>(ah, al, wth + 3 * wsz, wtl + 3 * wsz, bo, out, MM);
}